// round 1
// baseline (speedup 1.0000x reference)
#include <cuda_runtime.h>

#define SL   3264            // seq length L
#define KK   12
#define LPK  (SL / KK)       // 272
#define SS   8               // streams
#define BB   64              // batch
#define AA   4               // antennas
#define RR   (SL / 4)        // 816 (L / LOCC)
#define NOFF 21              // delay candidates -10..10

// ---- scratch (device-global: allocation-free contract) ----
__device__ float2 g_tw[SL];                       // exp(i*2*pi*k/L)
__device__ int    g_m[SS * BB];                   // (t_off + ideal_peak) mod L, >=0
__device__ int    g_tt[SS * BB];                  // t_off mod L, >=0
__device__ float2 g_havg[SS * BB * AA * RR];      // OCC-averaged channel, 13.4 MB

// ---------------------------------------------------------------------------
// k0: twiddle table. exp(i * (2*pi/L) * k), matching the reference's
//     float32 angle = float32(2*pi/L) * k formula exactly.
// ---------------------------------------------------------------------------
__global__ void k_table() {
    const float W = (float)(6.283185307179586476925286766559 / (double)SL);
    for (int k = threadIdx.x; k < SL; k += blockDim.x) {
        float s, c;
        sincosf(W * (float)k, &s, &c);
        g_tw[k] = make_float2(c, s);
    }
}

// ---------------------------------------------------------------------------
// k1: timing-offset search. One block per (s,b); warp w evaluates the DFT
//     (ifft sign: +i exponent) at candidate bin n = (ideal_peak + w-10) mod L
//     for all 4 antennas, sums |.|^2, block-argmax picks t_off.
//     1/L scaling omitted (argmax-invariant).
// ---------------------------------------------------------------------------
__global__ void __launch_bounds__(NOFF * 32)
k_toff(const float* __restrict__ lsr, const float* __restrict__ lsi,
       const int* __restrict__ cs) {
    int sb   = blockIdx.x;            // s*BB + b
    int s    = sb / BB;
    int w    = threadIdx.x >> 5;
    int lane = threadIdx.x & 31;

    __shared__ float pow_sh[NOFF];

    int ideal = ((KK - cs[s]) % KK) * LPK;     // KK-cs in [1..KK] -> nonneg mod

    // candidate bin, normalized to [0, L)
    int n = ideal + (w - 10);
    n = ((n % SL) + SL) % SL;

    float acc[2 * AA];
#pragma unroll
    for (int i = 0; i < 2 * AA; i++) acc[i] = 0.0f;

    int idx  = (lane * n) % SL;        // lane*n < 32*3264, fits int32
    int step = (32 * n) % SL;

    const float* br = lsr + (size_t)sb * (AA * SL);
    const float* bi = lsi + (size_t)sb * (AA * SL);

    for (int l = lane; l < SL; l += 32) {
        float2 tw = g_tw[idx];
#pragma unroll
        for (int a = 0; a < AA; a++) {
            float xr = br[a * SL + l];
            float xi = bi[a * SL + l];
            acc[2 * a]     += xr * tw.x - xi * tw.y;   // re of x*e^{+i th}
            acc[2 * a + 1] += xr * tw.y + xi * tw.x;   // im
        }
        idx += step;
        if (idx >= SL) idx -= SL;
    }

    // warp-reduce the 4 complex sums, then power
    float p = 0.0f;
#pragma unroll
    for (int a = 0; a < AA; a++) {
        float re = acc[2 * a], im = acc[2 * a + 1];
#pragma unroll
        for (int o = 16; o > 0; o >>= 1) {
            re += __shfl_xor_sync(0xFFFFFFFFu, re, o);
            im += __shfl_xor_sync(0xFFFFFFFFu, im, o);
        }
        p += re * re + im * im;
    }
    if (lane == 0) pow_sh[w] = p;
    __syncthreads();

    if (threadIdx.x == 0) {
        int   best = 0;
        float bp   = pow_sh[0];
        for (int j = 1; j < NOFF; j++)
            if (pow_sh[j] > bp) { bp = pow_sh[j]; best = j; }   // first-max tie rule
        int toff = best - 10;
        g_m[sb]  = (((toff + ideal) % SL) + SL) % SL;
        g_tt[sb] = ((toff % SL) + SL) % SL;
    }
}

// ---------------------------------------------------------------------------
// k2: h_avg[s,b,a,r] = (1/4) * sum_{j=0..3} ls[s,b,a,4r+j] * ph_m[s,b,4r+j]
// ---------------------------------------------------------------------------
__global__ void __launch_bounds__(256)
k_havg(const float* __restrict__ lsr, const float* __restrict__ lsi) {
    int e = blockIdx.x * blockDim.x + threadIdx.x;
    if (e >= SS * BB * AA * RR) return;
    int r   = e % RR;
    int sba = e / RR;                 // (s*BB+b)*AA + a
    int sb  = sba / AA;

    int mm = g_m[sb];
    const float* br = lsr + (size_t)sba * SL;
    const float* bi = lsi + (size_t)sba * SL;

    int l0  = 4 * r;
    int idx = (mm * l0) % SL;         // < 3264*3264 ~ 10.6M, fits int32
    float sr = 0.0f, si = 0.0f;
#pragma unroll
    for (int j = 0; j < 4; j++) {
        float2 tw = g_tw[idx];
        float  xr = br[l0 + j];
        float  xi = bi[l0 + j];
        sr += xr * tw.x - xi * tw.y;
        si += xr * tw.y + xi * tw.x;
        idx += mm;
        if (idx >= SL) idx -= SL;
    }
    g_havg[e] = make_float2(sr * 0.25f, si * 0.25f);
}

// ---------------------------------------------------------------------------
// k3: per (b,a,l): interp all 8 streams, accumulate total_recon, residual
//     against ls[0], then final = (h_interp + residual*ph_m) * conj(ph_T).
//     Output layout [2, S, B, A, L].
// ---------------------------------------------------------------------------
__global__ void __launch_bounds__(256)
k_final(const float* __restrict__ lsr, const float* __restrict__ lsi,
        float* __restrict__ out) {
    int e = blockIdx.x * blockDim.x + threadIdx.x;
    const int TOT = BB * AA * SL;
    if (e >= TOT) return;
    int l  = e % SL;
    int ba = e / SL;                  // b*AA + a
    int a  = ba % AA;
    int b  = ba / AA;

    // interpolation coordinates (float32, matching reference exactly)
    float t = ((float)l - 1.5f) * 0.25f;
    t = fminf(fmaxf(t, 0.0f), (float)(RR - 1));
    int   i0   = (int)t;              // t >= 0, floor == trunc
    float frac = t - (float)i0;
    int   i1   = min(i0 + 1, RR - 1);
    float omf  = 1.0f - frac;

    float hir[SS], hii[SS], pmr[SS], pmi[SS];
    float rre = 0.0f, rim = 0.0f;

#pragma unroll
    for (int s = 0; s < SS; s++) {
        int sb = s * BB + b;
        const float2* hv = g_havg + ((size_t)(sb * AA + a)) * RR;
        float2 h0 = hv[i0];
        float2 h1 = hv[i1];
        float hr = h0.x * omf + h1.x * frac;
        float hi = h0.y * omf + h1.y * frac;

        int    mm = g_m[sb];
        float2 pm = g_tw[(mm * l) % SL];

        hir[s] = hr; hii[s] = hi; pmr[s] = pm.x; pmi[s] = pm.y;

        // total_recon += h_interp * conj(ph_m)
        rre += hr * pm.x + hi * pm.y;
        rim += hi * pm.x - hr * pm.y;
    }

    // residual = ls[0,b,a,l] - total_recon
    float x0r  = lsr[(size_t)ba * SL + l];
    float x0i  = lsi[(size_t)ba * SL + l];
    float resr = x0r - rre;
    float resi = x0i - rim;

#pragma unroll
    for (int s = 0; s < SS; s++) {
        int    sb = s * BB + b;
        int    tt = g_tt[sb];
        float2 pt = g_tw[(tt * l) % SL];

        // w = h_interp + residual * ph_m
        float wr = hir[s] + resr * pmr[s] - resi * pmi[s];
        float wi = hii[s] + resr * pmi[s] + resi * pmr[s];
        // out = w * conj(ph_T)
        float outr = wr * pt.x + wi * pt.y;
        float outi = wi * pt.x - wr * pt.y;

        size_t off = ((size_t)(sb * AA + a)) * SL + (size_t)l;
        out[off]                              = outr;
        out[(size_t)SS * BB * AA * SL + off]  = outi;
    }
}

// ---------------------------------------------------------------------------
extern "C" void kernel_launch(void* const* d_in, const int* in_sizes, int n_in,
                              void* d_out, int out_size) {
    (void)in_sizes; (void)n_in; (void)out_size;
    const float* lsr = (const float*)d_in[0];
    const float* lsi = (const float*)d_in[1];
    const int*   cs  = (const int*)d_in[2];
    float*       out = (float*)d_out;

    k_table<<<1, 256>>>();
    k_toff<<<SS * BB, NOFF * 32>>>(lsr, lsi, cs);

    int n2 = SS * BB * AA * RR;
    k_havg<<<(n2 + 255) / 256, 256>>>(lsr, lsi);

    int n3 = BB * AA * SL;
    k_final<<<(n3 + 255) / 256, 256>>>(lsr, lsi, out);
}

// round 2
// speedup vs baseline: 3.2197x; 3.2197x over previous
#include <cuda_runtime.h>
#include <cstdint>

#define SL   3264            // seq length L
#define KK   12
#define LPK  (SL / KK)       // 272
#define SS   8               // streams
#define BB   64              // batch
#define AA   4               // antennas
#define RR   (SL / 4)        // 816 (L / LOCC)
#define NOFF 21              // delay candidates -10..10

// ---- scratch (device-global: allocation-free contract) ----
__device__ float2 g_tw[SL];                       // exp(i*2*pi*k/L)
__device__ int    g_m[SS * BB];                   // (t_off + ideal_peak) mod L, >=0
__device__ int    g_tt[SS * BB];                  // t_off mod L, >=0
__device__ float2 g_havg[SS * BB * AA * RR];      // OCC-averaged channel, 13.4 MB

// ---- packed f32x2 helpers (sm_103a dual-lane fp32) ----
#define F2MUL(o, a, b)    asm("mul.rn.f32x2 %0, %1, %2;"      : "=l"(o) : "l"(a), "l"(b))
#define F2FMA(o, a, b, c) asm("fma.rn.f32x2 %0, %1, %2, %3;"  : "=l"(o) : "l"(a), "l"(b), "l"(c))
#define F2ADD(o, a, b)    asm("add.rn.f32x2 %0, %1, %2;"      : "=l"(o) : "l"(a), "l"(b))
#define SGNMASK 0x8000000080000000ULL

static __device__ __forceinline__ uint64_t pk2(float lo, float hi) {
    uint64_t r; asm("mov.b64 %0, {%1, %2};" : "=l"(r) : "f"(lo), "f"(hi)); return r;
}
static __device__ __forceinline__ float lo2(uint64_t v) {
    float a, b; asm("mov.b64 {%0, %1}, %2;" : "=f"(a), "=f"(b) : "l"(v)); return a;
}
static __device__ __forceinline__ float hi2(uint64_t v) {
    float a, b; asm("mov.b64 {%0, %1}, %2;" : "=f"(a), "=f"(b) : "l"(v)); return b;
}

// ---------------------------------------------------------------------------
// k0: twiddle table. exp(i * float32(2*pi/L) * k), matching reference fp32 math.
// ---------------------------------------------------------------------------
__global__ void k_table() {
    const float W = (float)(6.283185307179586476925286766559 / (double)SL);
    for (int k = threadIdx.x; k < SL; k += blockDim.x) {
        float s, c;
        sincosf(W * (float)k, &s, &c);
        g_tw[k] = make_float2(c, s);
    }
}

// ---------------------------------------------------------------------------
// k1: timing-offset search, packed-f32x2 register-resident version.
//   Block per (s,b). 8 warps: antenna a = w>>1, half h = w&1.
//   Each thread holds 21 complex accumulators (packed over 2 adjacent l's)
//   and advances phasors c = e^{i th n0 l}, u = e^{i th l} by recurrence.
//   X(n0+d) = sum_l (x_l * c_l) * u_l^d,  power = sum_a |X_a|^2, argmax d.
// ---------------------------------------------------------------------------
__global__ void __launch_bounds__(256)
k_toff(const float* __restrict__ lsr, const float* __restrict__ lsi,
       const int* __restrict__ cs) {
    const int sb   = blockIdx.x;
    const int s    = sb / BB;
    const int w    = threadIdx.x >> 5;
    const int lane = threadIdx.x & 31;
    const int a    = w >> 1;
    const int h    = w & 1;

    __shared__ float2 sh[8][NOFF];
    __shared__ float  shpow[NOFF];

    const int ideal = ((KK - cs[s]) % KK) * LPK;   // in [0, SL)
    const int n0    = ideal;                        // exp periodic; use directly

    const float* br = lsr + ((size_t)sb * AA + a) * SL;
    const float* bi = lsi + ((size_t)sb * AA + a) * SL;

    // thread strip: pairs (l, l+1), l = h*64 + lane*2, stride 128
    int l = h * 64 + lane * 2;

    // init phasors from table
    int ci0 = (n0 * l) % SL;
    int ci1 = ci0 + n0; if (ci1 >= SL) ci1 -= SL;
    float2 cl = g_tw[ci0], ch = g_tw[ci1];
    uint64_t cr2 = pk2(cl.x, ch.x);
    uint64_t ci2 = pk2(cl.y, ch.y);
    float2 ul = g_tw[l], uh = g_tw[l + 1];
    uint64_t ur2 = pk2(ul.x, uh.x);
    uint64_t ui2 = pk2(ul.y, uh.y);

    // per-iteration steps (uniform): e^{i th n0*128}, e^{i th 128}
    float2 scv = g_tw[(n0 * 128) % SL];
    float2 suv = g_tw[128];
    uint64_t scr2 = pk2(scv.x, scv.x), sci2 = pk2(scv.y, scv.y);
    uint64_t sur2 = pk2(suv.x, suv.x), sui2 = pk2(suv.y, suv.y);
    uint64_t nsci2 = sci2 ^ SGNMASK;
    uint64_t nsui2 = sui2 ^ SGNMASK;

    uint64_t accr[NOFF], acci[NOFF];
#pragma unroll
    for (int d = 0; d < NOFF; d++) { accr[d] = 0ULL; acci[d] = 0ULL; }

    for (; l < SL; l += 128) {
        uint64_t xr2 = *(const uint64_t*)(br + l);
        uint64_t xi2 = *(const uint64_t*)(bi + l);
        uint64_t nci2 = ci2 ^ SGNMASK;
        uint64_t nui2 = ui2 ^ SGNMASK;

        // z = x * c
        uint64_t t, t2, zr2, zi2;
        F2MUL(t,  xi2, nci2);
        F2MUL(t2, xi2, cr2);
        F2FMA(zr2, xr2, cr2, t);
        F2FMA(zi2, xr2, ci2, t2);

        F2ADD(accr[10], accr[10], zr2);
        F2ADD(acci[10], acci[10], zi2);

        uint64_t wpr = zr2, wpi = zi2;   // forward chain  (* u)
        uint64_t wmr = zr2, wmi = zi2;   // backward chain (* conj(u))
#pragma unroll
        for (int d = 1; d <= 10; d++) {
            uint64_t m1, m2, nr;
            // wp *= u
            F2MUL(m1, wpi, nui2);
            F2MUL(m2, wpi, ur2);
            F2FMA(nr,  wpr, ur2, m1);
            F2FMA(wpi, wpr, ui2, m2);
            wpr = nr;
            F2ADD(accr[10 + d], accr[10 + d], wpr);
            F2ADD(acci[10 + d], acci[10 + d], wpi);
            // wm *= conj(u)
            F2MUL(m1, wmi, ui2);
            F2MUL(m2, wmi, ur2);
            F2FMA(nr,  wmr, ur2, m1);
            F2FMA(wmi, wmr, nui2, m2);
            wmr = nr;
            F2ADD(accr[10 - d], accr[10 - d], wmr);
            F2ADD(acci[10 - d], acci[10 - d], wmi);
        }

        // c *= sc ; u *= su
        uint64_t m1, m2, nr;
        F2MUL(m1, ci2, nsci2);
        F2MUL(m2, ci2, scr2);
        F2FMA(nr,  cr2, scr2, m1);
        F2FMA(ci2, cr2, sci2, m2);
        cr2 = nr;
        F2MUL(m1, ui2, nsui2);
        F2MUL(m2, ui2, sur2);
        F2FMA(nr,  ur2, sur2, m1);
        F2FMA(ui2, ur2, sui2, m2);
        ur2 = nr;
    }

    // reduce: packed halves -> scalar, warp shfl-sum, stash per warp
#pragma unroll
    for (int d = 0; d < NOFF; d++) {
        float rr = lo2(accr[d]) + hi2(accr[d]);
        float ii = lo2(acci[d]) + hi2(acci[d]);
#pragma unroll
        for (int o = 16; o > 0; o >>= 1) {
            rr += __shfl_xor_sync(0xFFFFFFFFu, rr, o);
            ii += __shfl_xor_sync(0xFFFFFFFFu, ii, o);
        }
        if (lane == 0) sh[w][d] = make_float2(rr, ii);
    }
    __syncthreads();

    if (threadIdx.x < NOFF) {
        int d = threadIdx.x;
        float p = 0.0f;
#pragma unroll
        for (int aa = 0; aa < AA; aa++) {
            float re = sh[2 * aa][d].x + sh[2 * aa + 1][d].x;
            float im = sh[2 * aa][d].y + sh[2 * aa + 1][d].y;
            p += re * re + im * im;
        }
        shpow[d] = p;
    }
    __syncthreads();

    if (threadIdx.x == 0) {
        int   best = 0;
        float bp   = shpow[0];
        for (int j = 1; j < NOFF; j++)
            if (shpow[j] > bp) { bp = shpow[j]; best = j; }  // first-max tie rule
        int toff = best - 10;
        g_m[sb]  = (((toff + ideal) % SL) + SL) % SL;
        g_tt[sb] = ((toff % SL) + SL) % SL;
    }
}

// ---------------------------------------------------------------------------
// k2: h_avg[s,b,a,r] = (1/4) * sum_{j=0..3} ls[s,b,a,4r+j] * ph_m[s,b,4r+j]
// ---------------------------------------------------------------------------
__global__ void __launch_bounds__(256)
k_havg(const float* __restrict__ lsr, const float* __restrict__ lsi) {
    int e = blockIdx.x * blockDim.x + threadIdx.x;
    if (e >= SS * BB * AA * RR) return;
    int r   = e % RR;
    int sba = e / RR;
    int sb  = sba / AA;

    int mm = g_m[sb];
    const float* br = lsr + (size_t)sba * SL;
    const float* bi = lsi + (size_t)sba * SL;

    int l0 = 4 * r;
    float4 xr = *(const float4*)(br + l0);
    float4 xi = *(const float4*)(bi + l0);

    int idx = (mm * l0) % SL;
    float sr = 0.0f, si = 0.0f;
    float xrv[4] = {xr.x, xr.y, xr.z, xr.w};
    float xiv[4] = {xi.x, xi.y, xi.z, xi.w};
#pragma unroll
    for (int j = 0; j < 4; j++) {
        float2 tw = g_tw[idx];
        sr += xrv[j] * tw.x - xiv[j] * tw.y;
        si += xrv[j] * tw.y + xiv[j] * tw.x;
        idx += mm;
        if (idx >= SL) idx -= SL;
    }
    g_havg[e] = make_float2(sr * 0.25f, si * 0.25f);
}

// ---------------------------------------------------------------------------
// k3: per (b,a,l): interp all 8 streams, residual vs ls[0], final rotate.
// ---------------------------------------------------------------------------
__global__ void __launch_bounds__(256)
k_final(const float* __restrict__ lsr, const float* __restrict__ lsi,
        float* __restrict__ out) {
    int e = blockIdx.x * blockDim.x + threadIdx.x;
    const int TOT = BB * AA * SL;
    if (e >= TOT) return;
    int l  = e % SL;
    int ba = e / SL;
    int a  = ba % AA;
    int b  = ba / AA;

    float t = ((float)l - 1.5f) * 0.25f;
    t = fminf(fmaxf(t, 0.0f), (float)(RR - 1));
    int   i0   = (int)t;
    float frac = t - (float)i0;
    int   i1   = min(i0 + 1, RR - 1);
    float omf  = 1.0f - frac;

    float hir[SS], hii[SS], pmr[SS], pmi[SS];
    float rre = 0.0f, rim = 0.0f;

#pragma unroll
    for (int s = 0; s < SS; s++) {
        int sb = s * BB + b;
        const float2* hv = g_havg + ((size_t)(sb * AA + a)) * RR;
        float2 h0 = hv[i0];
        float2 h1 = hv[i1];
        float hr = h0.x * omf + h1.x * frac;
        float hi = h0.y * omf + h1.y * frac;

        int    mm = g_m[sb];
        float2 pm = g_tw[(mm * l) % SL];

        hir[s] = hr; hii[s] = hi; pmr[s] = pm.x; pmi[s] = pm.y;

        rre += hr * pm.x + hi * pm.y;
        rim += hi * pm.x - hr * pm.y;
    }

    float x0r  = lsr[(size_t)ba * SL + l];
    float x0i  = lsi[(size_t)ba * SL + l];
    float resr = x0r - rre;
    float resi = x0i - rim;

#pragma unroll
    for (int s = 0; s < SS; s++) {
        int    sb = s * BB + b;
        int    tt = g_tt[sb];
        float2 pt = g_tw[(tt * l) % SL];

        float wr = hir[s] + resr * pmr[s] - resi * pmi[s];
        float wi = hii[s] + resr * pmi[s] + resi * pmr[s];
        float outr = wr * pt.x + wi * pt.y;
        float outi = wi * pt.x - wr * pt.y;

        size_t off = ((size_t)(sb * AA + a)) * SL + (size_t)l;
        out[off]                             = outr;
        out[(size_t)SS * BB * AA * SL + off] = outi;
    }
}

// ---------------------------------------------------------------------------
extern "C" void kernel_launch(void* const* d_in, const int* in_sizes, int n_in,
                              void* d_out, int out_size) {
    (void)in_sizes; (void)n_in; (void)out_size;
    const float* lsr = (const float*)d_in[0];
    const float* lsi = (const float*)d_in[1];
    const int*   cs  = (const int*)d_in[2];
    float*       out = (float*)d_out;

    k_table<<<1, 256>>>();
    k_toff<<<SS * BB, 256>>>(lsr, lsi, cs);

    int n2 = SS * BB * AA * RR;
    k_havg<<<(n2 + 255) / 256, 256>>>(lsr, lsi);

    int n3 = BB * AA * SL;
    k_final<<<(n3 + 255) / 256, 256>>>(lsr, lsi, out);
}

// round 3
// speedup vs baseline: 3.5395x; 1.0993x over previous
#include <cuda_runtime.h>
#include <cstdint>

#define SL   3264            // seq length L
#define KK   12
#define LPK  (SL / KK)       // 272
#define SS   8               // streams
#define BB   64              // batch
#define AA   4               // antennas
#define RR   (SL / 4)        // 816 (L / LOCC)
#define NOFF 21              // delay candidates -10..10
#define TILE 128             // l-tile for k_final
#define NTILE 26             // ceil(3264/128)

// ---- scratch (device-global: allocation-free contract) ----
__device__ float2 g_tw[SL];                       // exp(i*2*pi*k/L)
__device__ int    g_m[SS * BB];                   // (t_off + ideal_peak) mod L, >=0
__device__ int    g_tt[SS * BB];                  // t_off mod L, >=0
__device__ float2 g_havg[SS * BB * AA * RR];      // OCC-averaged channel, 13.4 MB

// ---- packed f32x2 helpers (sm_103a dual-lane fp32) ----
#define F2MUL(o, a, b)    asm("mul.rn.f32x2 %0, %1, %2;"      : "=l"(o) : "l"(a), "l"(b))
#define F2FMA(o, a, b, c) asm("fma.rn.f32x2 %0, %1, %2, %3;"  : "=l"(o) : "l"(a), "l"(b), "l"(c))
#define F2ADD(o, a, b)    asm("add.rn.f32x2 %0, %1, %2;"      : "=l"(o) : "l"(a), "l"(b))
#define SGNMASK 0x8000000080000000ULL

static __device__ __forceinline__ uint64_t pk2(float lo, float hi) {
    uint64_t r; asm("mov.b64 %0, {%1, %2};" : "=l"(r) : "f"(lo), "f"(hi)); return r;
}
static __device__ __forceinline__ float lo2(uint64_t v) {
    float a, b; asm("mov.b64 {%0, %1}, %2;" : "=f"(a), "=f"(b) : "l"(v)); return a;
}
static __device__ __forceinline__ float hi2(uint64_t v) {
    float a, b; asm("mov.b64 {%0, %1}, %2;" : "=f"(a), "=f"(b) : "l"(v)); return b;
}

// ---------------------------------------------------------------------------
// k0: twiddle table. exp(i * float32(2*pi/L) * k).
// ---------------------------------------------------------------------------
__global__ void k_table() {
    const float W = (float)(6.283185307179586476925286766559 / (double)SL);
    int k = blockIdx.x * blockDim.x + threadIdx.x;
    if (k < SL) {
        float s, c;
        sincosf(W * (float)k, &s, &c);
        g_tw[k] = make_float2(c, s);
    }
}

// ---------------------------------------------------------------------------
// k_main: fused timing-offset search (phase A) + OCC averaging (phase B).
//   One block per (s,b). Phase A: packed-f32x2 DFT at 21 candidate bins via
//   phasor recurrences, all accumulators register-resident; argmax -> t_off.
//   Phase B: h_avg from the same (L2-hot) data using the chosen m.
// ---------------------------------------------------------------------------
__global__ void __launch_bounds__(256)
k_main(const float* __restrict__ lsr, const float* __restrict__ lsi,
       const int* __restrict__ cs) {
    const int sb   = blockIdx.x;
    const int s    = sb / BB;
    const int w    = threadIdx.x >> 5;
    const int lane = threadIdx.x & 31;
    const int a    = w >> 1;
    const int h    = w & 1;

    __shared__ float2 sh[8][NOFF];
    __shared__ float  shpow[NOFF];
    __shared__ int    sh_mm;

    const int ideal = ((KK - cs[s]) % KK) * LPK;   // in [0, SL)
    const int n0    = ideal;

    const float* br = lsr + ((size_t)sb * AA + a) * SL;
    const float* bi = lsi + ((size_t)sb * AA + a) * SL;

    // thread strip: pairs (l, l+1), l = h*64 + lane*2, stride 128
    int l = h * 64 + lane * 2;
    const int lstart = l;

    // init phasors from table
    int ci0 = (n0 * l) % SL;
    int ci1 = ci0 + n0; if (ci1 >= SL) ci1 -= SL;
    float2 cl = g_tw[ci0], ch = g_tw[ci1];
    uint64_t cr2 = pk2(cl.x, ch.x);
    uint64_t ci2 = pk2(cl.y, ch.y);
    float2 ul = g_tw[l], uh = g_tw[l + 1];
    uint64_t ur2 = pk2(ul.x, uh.x);
    uint64_t ui2 = pk2(ul.y, uh.y);

    // per-iteration steps (uniform)
    float2 scv = g_tw[(n0 * 128) % SL];
    float2 suv = g_tw[128];
    uint64_t scr2 = pk2(scv.x, scv.x), sci2 = pk2(scv.y, scv.y);
    uint64_t sur2 = pk2(suv.x, suv.x), sui2 = pk2(suv.y, suv.y);
    uint64_t nsci2 = sci2 ^ SGNMASK;
    uint64_t nsui2 = sui2 ^ SGNMASK;

    uint64_t accr[NOFF], acci[NOFF];
#pragma unroll
    for (int d = 0; d < NOFF; d++) { accr[d] = 0ULL; acci[d] = 0ULL; }

    // software-pipelined data loads
    uint64_t xr2 = *(const uint64_t*)(br + l);
    uint64_t xi2 = *(const uint64_t*)(bi + l);

    for (; l < SL; ) {
        int ln = l + 128;
        uint64_t nxr = 0, nxi = 0;
        if (ln < SL) {
            nxr = *(const uint64_t*)(br + ln);
            nxi = *(const uint64_t*)(bi + ln);
        }

        uint64_t nci2 = ci2 ^ SGNMASK;
        uint64_t nui2 = ui2 ^ SGNMASK;

        // z = x * c
        uint64_t t, t2, zr2, zi2;
        F2MUL(t,  xi2, nci2);
        F2MUL(t2, xi2, cr2);
        F2FMA(zr2, xr2, cr2, t);
        F2FMA(zi2, xr2, ci2, t2);

        F2ADD(accr[10], accr[10], zr2);
        F2ADD(acci[10], acci[10], zi2);

        uint64_t wpr = zr2, wpi = zi2;   // forward chain  (* u)
        uint64_t wmr = zr2, wmi = zi2;   // backward chain (* conj(u))
#pragma unroll
        for (int d = 1; d <= 10; d++) {
            uint64_t m1, m2, nr;
            F2MUL(m1, wpi, nui2);
            F2MUL(m2, wpi, ur2);
            F2FMA(nr,  wpr, ur2, m1);
            F2FMA(wpi, wpr, ui2, m2);
            wpr = nr;
            F2ADD(accr[10 + d], accr[10 + d], wpr);
            F2ADD(acci[10 + d], acci[10 + d], wpi);
            F2MUL(m1, wmi, ui2);
            F2MUL(m2, wmi, ur2);
            F2FMA(nr,  wmr, ur2, m1);
            F2FMA(wmi, wmr, nui2, m2);
            wmr = nr;
            F2ADD(accr[10 - d], accr[10 - d], wmr);
            F2ADD(acci[10 - d], acci[10 - d], wmi);
        }

        // c *= sc ; u *= su
        uint64_t m1, m2, nr;
        F2MUL(m1, ci2, nsci2);
        F2MUL(m2, ci2, scr2);
        F2FMA(nr,  cr2, scr2, m1);
        F2FMA(ci2, cr2, sci2, m2);
        cr2 = nr;
        F2MUL(m1, ui2, nsui2);
        F2MUL(m2, ui2, sur2);
        F2FMA(nr,  ur2, sur2, m1);
        F2FMA(ui2, ur2, sui2, m2);
        ur2 = nr;

        xr2 = nxr; xi2 = nxi;
        l = ln;
    }
    (void)lstart;

    // reduce: packed halves -> scalar, warp shfl-sum, stash per warp
#pragma unroll
    for (int d = 0; d < NOFF; d++) {
        float rr = lo2(accr[d]) + hi2(accr[d]);
        float ii = lo2(acci[d]) + hi2(acci[d]);
#pragma unroll
        for (int o = 16; o > 0; o >>= 1) {
            rr += __shfl_xor_sync(0xFFFFFFFFu, rr, o);
            ii += __shfl_xor_sync(0xFFFFFFFFu, ii, o);
        }
        if (lane == 0) sh[w][d] = make_float2(rr, ii);
    }
    __syncthreads();

    if (threadIdx.x < NOFF) {
        int d = threadIdx.x;
        float p = 0.0f;
#pragma unroll
        for (int aa = 0; aa < AA; aa++) {
            float re = sh[2 * aa][d].x + sh[2 * aa + 1][d].x;
            float im = sh[2 * aa][d].y + sh[2 * aa + 1][d].y;
            p += re * re + im * im;
        }
        shpow[d] = p;
    }
    __syncthreads();

    if (threadIdx.x == 0) {
        int   best = 0;
        float bp   = shpow[0];
        for (int j = 1; j < NOFF; j++)
            if (shpow[j] > bp) { bp = shpow[j]; best = j; }  // first-max tie rule
        int toff = best - 10;
        int mmv  = (((toff + ideal) % SL) + SL) % SL;
        g_m[sb]  = mmv;
        g_tt[sb] = ((toff % SL) + SL) % SL;
        sh_mm    = mmv;
    }
    __syncthreads();

    // ---- phase B: OCC averaging for this (s,b), data L2-hot ----
    const int mmv = sh_mm;
#pragma unroll
    for (int a2 = 0; a2 < AA; a2++) {
        const float* br2 = lsr + ((size_t)sb * AA + a2) * SL;
        const float* bi2 = lsi + ((size_t)sb * AA + a2) * SL;
        float2* ho = g_havg + ((size_t)sb * AA + a2) * RR;
        for (int r = threadIdx.x; r < RR; r += 256) {
            int l0 = 4 * r;
            float4 xr = *(const float4*)(br2 + l0);
            float4 xi = *(const float4*)(bi2 + l0);
            int idx = (mmv * l0) % SL;
            float xrv[4] = {xr.x, xr.y, xr.z, xr.w};
            float xiv[4] = {xi.x, xi.y, xi.z, xi.w};
            float sr = 0.0f, si = 0.0f;
#pragma unroll
            for (int j = 0; j < 4; j++) {
                float2 tw = g_tw[idx];
                sr += xrv[j] * tw.x - xiv[j] * tw.y;
                si += xrv[j] * tw.y + xiv[j] * tw.x;
                idx += mmv;
                if (idx >= SL) idx -= SL;
            }
            ho[r] = make_float2(sr * 0.25f, si * 0.25f);
        }
    }
}

// ---------------------------------------------------------------------------
// k_final: warp-per-stream over a 128-l tile for one (b,a).
//   Pass 1: each warp computes h_interp + ph_m for its stream (4 l's/lane),
//   stores recon contributions to smem. Reduction forms residual. Pass 2
//   reuses register-resident h/pm, rotates by conj(ph_T), STG.128 outputs.
// ---------------------------------------------------------------------------
__global__ void __launch_bounds__(256)
k_final(const float* __restrict__ lsr, const float* __restrict__ lsi,
        float* __restrict__ out) {
    const int blk  = blockIdx.x;
    const int ba   = blk / NTILE;
    const int tile = blk % NTILE;
    const int a    = ba % AA;
    const int b    = ba / AA;
    const int s    = threadIdx.x >> 5;   // warp = stream
    const int lane = threadIdx.x & 31;

    const int lbase = tile * TILE;
    const int l0    = lbase + lane * 4;
    const bool act  = (l0 < SL);

    __shared__ float shc[SS][2 * TILE];   // recon contributions
    __shared__ float shres[2 * TILE];     // residual

    const int sb = s * BB + b;
    const int mm = g_m[sb];
    const int tt = g_tt[sb];
    const float2* hv = g_havg + ((size_t)sb * AA + a) * RR;

    float hr[4], hi[4], pr[4], pi[4];

    if (act) {
        int g = l0 >> 2;
        float2 hm = hv[max(g - 1, 0)];
        float2 h0 = hv[g];
        float2 hp = hv[min(g + 1, RR - 1)];

        float f0 = (g > 0)      ? 0.625f : 0.0f;
        float f1 = (g > 0)      ? 0.875f : 0.0f;
        float f2 = (g < RR - 1) ? 0.125f : 0.0f;
        float f3 = (g < RR - 1) ? 0.375f : 0.0f;

        hr[0] = hm.x * (1.0f - f0) + h0.x * f0;  hi[0] = hm.y * (1.0f - f0) + h0.y * f0;
        hr[1] = hm.x * (1.0f - f1) + h0.x * f1;  hi[1] = hm.y * (1.0f - f1) + h0.y * f1;
        hr[2] = h0.x * (1.0f - f2) + hp.x * f2;  hi[2] = h0.y * (1.0f - f2) + hp.y * f2;
        hr[3] = h0.x * (1.0f - f3) + hp.x * f3;  hi[3] = h0.y * (1.0f - f3) + hp.y * f3;

        float2 pm = g_tw[(mm * l0) % SL];
        float2 ms = g_tw[mm];
        float cr[4], cc[4];
#pragma unroll
        for (int j = 0; j < 4; j++) {
            pr[j] = pm.x; pi[j] = pm.y;
            // recon contribution: h_interp * conj(ph_m)
            cr[j] = hr[j] * pm.x + hi[j] * pm.y;
            cc[j] = hi[j] * pm.x - hr[j] * pm.y;
            if (j < 3) {
                float nr = pm.x * ms.x - pm.y * ms.y;
                float ni = pm.x * ms.y + pm.y * ms.x;
                pm = make_float2(nr, ni);
            }
        }
        float4* dst = (float4*)&shc[s][lane * 8];
        dst[0] = make_float4(cr[0], cc[0], cr[1], cc[1]);
        dst[1] = make_float4(cr[2], cc[2], cr[3], cc[3]);
    }
    __syncthreads();

    // residual reduction: thread t -> (local l, component)
    {
        int ll   = threadIdx.x >> 1;
        int comp = threadIdx.x & 1;
        int lg   = lbase + ll;
        if (lg < SL) {
            float sum = 0.0f;
#pragma unroll
            for (int ss2 = 0; ss2 < SS; ss2++) sum += shc[ss2][ll * 2 + comp];
            const float* ls0 = comp ? lsi : lsr;
            shres[ll * 2 + comp] = ls0[(size_t)ba * SL + lg] - sum;
        }
    }
    __syncthreads();

    if (act) {
        float2 pt = g_tw[(tt * l0) % SL];
        float2 ts = g_tw[tt];

        float4 r01 = *(float4*)&shres[lane * 8];
        float4 r23 = *(float4*)&shres[lane * 8 + 4];
        float rres[4] = {r01.x, r01.z, r23.x, r23.z};
        float rims[4] = {r01.y, r01.w, r23.y, r23.w};

        float4 outr, outi;
        float* orp = &outr.x;
        float* oip = &outi.x;
#pragma unroll
        for (int j = 0; j < 4; j++) {
            // w = h_interp + residual * ph_m
            float wr = hr[j] + rres[j] * pr[j] - rims[j] * pi[j];
            float wi = hi[j] + rres[j] * pi[j] + rims[j] * pr[j];
            // out = w * conj(ph_T)
            orp[j] = wr * pt.x + wi * pt.y;
            oip[j] = wi * pt.x - wr * pt.y;
            if (j < 3) {
                float nr = pt.x * ts.x - pt.y * ts.y;
                float ni = pt.x * ts.y + pt.y * ts.x;
                pt = make_float2(nr, ni);
            }
        }

        const size_t TOT = (size_t)SS * BB * AA * SL;
        size_t off = ((size_t)sb * AA + a) * SL + (size_t)l0;
        *(float4*)(out + off)       = outr;
        *(float4*)(out + TOT + off) = outi;
    }
}

// ---------------------------------------------------------------------------
extern "C" void kernel_launch(void* const* d_in, const int* in_sizes, int n_in,
                              void* d_out, int out_size) {
    (void)in_sizes; (void)n_in; (void)out_size;
    const float* lsr = (const float*)d_in[0];
    const float* lsi = (const float*)d_in[1];
    const int*   cs  = (const int*)d_in[2];
    float*       out = (float*)d_out;

    k_table<<<13, 256>>>();
    k_main<<<SS * BB, 256>>>(lsr, lsi, cs);
    k_final<<<BB * AA * NTILE, 256>>>(lsr, lsi, out);
}

// round 4
// speedup vs baseline: 4.4207x; 1.2489x over previous
#include <cuda_runtime.h>
#include <cstdint>

#define SL   3264            // seq length L
#define KK   12
#define LPK  (SL / KK)       // 272
#define SS   8               // streams
#define BB   64              // batch
#define AA   4               // antennas
#define RR   (SL / 4)        // 816 (L / LOCC)
#define NOFF 21              // delay candidates -10..10
#define TILE 128             // l-tile for k_final
#define NTILE 26             // ceil(3264/128)
#define NITER 51             // SL / 64 l-pairs per warp

// ---- scratch (device-global: allocation-free contract) ----
__device__ int    g_m[SS * BB];                   // (t_off + ideal_peak) mod L
__device__ int    g_tt[SS * BB];                  // t_off mod L
__device__ float2 g_havg[SS * BB * AA * RR];      // OCC-averaged channel, 13.4 MB

// ---- packed f32x2 helpers (sm_103a dual-lane fp32) ----
#define F2MUL(o, a, b)    asm("mul.rn.f32x2 %0, %1, %2;"      : "=l"(o) : "l"(a), "l"(b))
#define F2FMA(o, a, b, c) asm("fma.rn.f32x2 %0, %1, %2, %3;"  : "=l"(o) : "l"(a), "l"(b), "l"(c))
#define F2ADD(o, a, b)    asm("add.rn.f32x2 %0, %1, %2;"      : "=l"(o) : "l"(a), "l"(b))
#define SGNMASK 0x8000000080000000ULL

static __device__ __forceinline__ uint64_t pk2(float lo, float hi) {
    uint64_t r; asm("mov.b64 %0, {%1, %2};" : "=l"(r) : "f"(lo), "f"(hi)); return r;
}
static __device__ __forceinline__ float lo2(uint64_t v) {
    float a, b; asm("mov.b64 {%0, %1}, %2;" : "=f"(a), "=f"(b) : "l"(v)); return a;
}
static __device__ __forceinline__ float hi2(uint64_t v) {
    float a, b; asm("mov.b64 {%0, %1}, %2;" : "=f"(a), "=f"(b) : "l"(v)); return b;
}

// fp32 2*pi/L, exactly round(2*pi/3264) like the reference
#define WF ((float)(6.283185307179586476925286766559 / 3264.0))

// ---------------------------------------------------------------------------
// k_main: fused timing-offset search (phase A, Chebyshev) + OCC avg (phase B).
//   One block per (s,b), 128 threads, warp = antenna, 4 blocks/SM (one wave).
// ---------------------------------------------------------------------------
__global__ void __launch_bounds__(128, 4)
k_main(const float* __restrict__ lsr, const float* __restrict__ lsi,
       const int* __restrict__ cs) {
    const int sb   = blockIdx.x;
    const int s    = sb / BB;
    const int a    = threadIdx.x >> 5;   // warp = antenna
    const int lane = threadIdx.x & 31;

    __shared__ float2 sh[AA][NOFF];
    __shared__ float  shpow[NOFF];
    __shared__ int    sh_mm;

    const int ideal = ((KK - cs[s]) % KK) * LPK;   // in [0, SL)
    const int n0    = ideal;

    const float* br = lsr + ((size_t)sb * AA + a) * SL;
    const float* bi = lsi + ((size_t)sb * AA + a) * SL;

    // ---- per-thread phasor seeds via sincosf (table-free) ----
    const int lp = lane * 2;              // l pair start; stride 64/iter
    float s0, c0, s1, c1;

    // u = e^{i th l}
    sincosf(WF * (float)lp, &s0, &c0);
    sincosf(WF * (float)(lp + 1), &s1, &c1);
    uint64_t ur2 = pk2(c0, c1), ui2 = pk2(s0, s1);

    // c = e^{i th (n0 l mod L)}  (chirp)
    int ca = (n0 * lp) % SL;
    int cb = ca + n0; if (cb >= SL) cb -= SL;
    sincosf(WF * (float)ca, &s0, &c0);
    sincosf(WF * (float)cb, &s1, &c1);
    uint64_t cr2 = pk2(c0, c1), ci2 = pk2(s0, s1);

    // steps: su = e^{i th 64}, sc = e^{i th (64 n0 mod L)}
    sincosf(WF * 64.0f, &s0, &c0);
    uint64_t sur2 = pk2(c0, c0), sui2 = pk2(s0, s0);
    sincosf(WF * (float)((n0 * 64) % SL), &s1, &c1);
    uint64_t scr2 = pk2(c1, c1), sci2 = pk2(s1, s1);

    uint64_t accr[NOFF], acci[NOFF];
#pragma unroll
    for (int d = 0; d < NOFF; d++) { accr[d] = 0ULL; acci[d] = 0ULL; }

    int l = lp;
#pragma unroll 1
    for (int it = 0; it < NITER; ++it) {
        uint64_t xr2 = *(const uint64_t*)(br + l);
        uint64_t xi2 = *(const uint64_t*)(bi + l);
        l += 64;

        // z = x * c
        uint64_t t1, t2, zr, zi;
        F2MUL(t1, xi2, ci2); t1 ^= SGNMASK;
        F2MUL(t2, xi2, cr2);
        F2FMA(zr, xr2, cr2, t1);
        F2FMA(zi, xr2, ci2, t2);

        F2ADD(accr[10], accr[10], zr);
        F2ADD(acci[10], acci[10], zi);

        // w1 = z * u
        uint64_t w1r, w1i;
        F2MUL(t1, zi, ui2); t1 ^= SGNMASK;
        F2MUL(t2, zi, ur2);
        F2FMA(w1r, zr, ur2, t1);
        F2FMA(w1i, zr, ui2, t2);

        F2ADD(accr[11], accr[11], w1r);
        F2ADD(acci[11], acci[11], w1i);

        // Chebyshev coefficient: tc = 2 Re(u); ntc = -tc
        uint64_t tc, ntc;
        F2ADD(tc, ur2, ur2);
        ntc = tc ^ SGNMASK;

        // forward chain: v_{d+1} = (+-tc) v_d + v_{d-1}; |acc| invariant to signs
        {
            uint64_t fpr = zr, fpi = zi, fcr = w1r, fci = w1i;
#pragma unroll
            for (int d = 1; d <= 9; ++d) {
                uint64_t co = (d & 1) ? ntc : tc;
                uint64_t nr, ni;
                F2FMA(nr, co, fcr, fpr);
                F2FMA(ni, co, fci, fpi);
                fpr = fcr; fpi = fci; fcr = nr; fci = ni;
                F2ADD(accr[11 + d], accr[11 + d], nr);
                F2ADD(acci[11 + d], acci[11 + d], ni);
            }
        }
        // backward chain: seed v'_1 = ntc*z + w1 ( = -w_{-1} )
        {
            uint64_t bpr = zr, bpi = zi, bcr, bci;
            F2FMA(bcr, ntc, zr, w1r);
            F2FMA(bci, ntc, zi, w1i);
            F2ADD(accr[9], accr[9], bcr);
            F2ADD(acci[9], acci[9], bci);
#pragma unroll
            for (int d = 1; d <= 9; ++d) {
                uint64_t co = (d & 1) ? tc : ntc;
                uint64_t nr, ni;
                F2FMA(nr, co, bcr, bpr);
                F2FMA(ni, co, bci, bpi);
                bpr = bcr; bpi = bci; bcr = nr; bci = ni;
                F2ADD(accr[9 - d], accr[9 - d], nr);
                F2ADD(acci[9 - d], acci[9 - d], ni);
            }
        }
        // u *= su ; c *= sc
        uint64_t nr;
        F2MUL(t1, ui2, sui2); t1 ^= SGNMASK;
        F2MUL(t2, ui2, sur2);
        F2FMA(nr,  ur2, sur2, t1);
        F2FMA(ui2, ur2, sui2, t2);
        ur2 = nr;
        F2MUL(t1, ci2, sci2); t1 ^= SGNMASK;
        F2MUL(t2, ci2, scr2);
        F2FMA(nr,  cr2, scr2, t1);
        F2FMA(ci2, cr2, sci2, t2);
        cr2 = nr;
    }

    // reduce: packed halves -> scalar, warp shfl-sum
#pragma unroll
    for (int d = 0; d < NOFF; d++) {
        float rr = lo2(accr[d]) + hi2(accr[d]);
        float ii = lo2(acci[d]) + hi2(acci[d]);
#pragma unroll
        for (int o = 16; o > 0; o >>= 1) {
            rr += __shfl_xor_sync(0xFFFFFFFFu, rr, o);
            ii += __shfl_xor_sync(0xFFFFFFFFu, ii, o);
        }
        if (lane == 0) sh[a][d] = make_float2(rr, ii);
    }
    __syncthreads();

    if (threadIdx.x < NOFF) {
        int d = threadIdx.x;
        float p = 0.0f;
#pragma unroll
        for (int aa = 0; aa < AA; aa++) {
            float re = sh[aa][d].x, im = sh[aa][d].y;
            p += re * re + im * im;
        }
        shpow[d] = p;
    }
    __syncthreads();

    if (threadIdx.x == 0) {
        int   best = 0;
        float bp   = shpow[0];
        for (int j = 1; j < NOFF; j++)
            if (shpow[j] > bp) { bp = shpow[j]; best = j; }  // first-max tie rule
        int toff = best - 10;
        int mmv  = (((toff + ideal) % SL) + SL) % SL;
        g_m[sb]  = mmv;
        g_tt[sb] = ((toff % SL) + SL) % SL;
        sh_mm    = mmv;
    }
    __syncthreads();

    // ---- phase B: OCC averaging, data L2-hot, phasors via sincosf+recurrence
    const int mmv = sh_mm;
    float mss, msc;
    sincosf(WF * (float)mmv, &mss, &msc);   // step e^{i th mm}

#pragma unroll
    for (int a2 = 0; a2 < AA; a2++) {
        const float* br2 = lsr + ((size_t)sb * AA + a2) * SL;
        const float* bi2 = lsi + ((size_t)sb * AA + a2) * SL;
        float2* ho = g_havg + ((size_t)sb * AA + a2) * RR;
        for (int r = threadIdx.x; r < RR; r += 128) {
            int l0 = 4 * r;
            float4 xr = *(const float4*)(br2 + l0);
            float4 xi = *(const float4*)(bi2 + l0);
            float ps, pc;
            sincosf(WF * (float)((mmv * l0) % SL), &ps, &pc);
            float xrv[4] = {xr.x, xr.y, xr.z, xr.w};
            float xiv[4] = {xi.x, xi.y, xi.z, xi.w};
            float sr = 0.0f, si = 0.0f;
#pragma unroll
            for (int j = 0; j < 4; j++) {
                sr += xrv[j] * pc - xiv[j] * ps;
                si += xrv[j] * ps + xiv[j] * pc;
                if (j < 3) {
                    float npc = pc * msc - ps * mss;
                    float nps = pc * mss + ps * msc;
                    pc = npc; ps = nps;
                }
            }
            ho[r] = make_float2(sr * 0.25f, si * 0.25f);
        }
    }
}

// ---------------------------------------------------------------------------
// k_final: warp-per-stream over a 128-l tile for one (b,a). Phasors via
//   sincosf seed + in-register recurrence (no scattered gathers).
// ---------------------------------------------------------------------------
__global__ void __launch_bounds__(256)
k_final(const float* __restrict__ lsr, const float* __restrict__ lsi,
        float* __restrict__ out) {
    const int blk  = blockIdx.x;
    const int ba   = blk / NTILE;
    const int tile = blk % NTILE;
    const int a    = ba % AA;
    const int b    = ba / AA;
    const int s    = threadIdx.x >> 5;   // warp = stream
    const int lane = threadIdx.x & 31;

    const int lbase = tile * TILE;
    const int l0    = lbase + lane * 4;
    const bool act  = (l0 < SL);

    __shared__ float shc[SS][2 * TILE];   // recon contributions
    __shared__ float shres[2 * TILE];     // residual

    const int sb = s * BB + b;
    const int mm = g_m[sb];
    const int tt = g_tt[sb];
    const float2* hv = g_havg + ((size_t)sb * AA + a) * RR;

    float hr[4], hi[4], pr[4], pi[4];

    if (act) {
        int g = l0 >> 2;
        float2 hm = hv[max(g - 1, 0)];
        float2 h0 = hv[g];
        float2 hp = hv[min(g + 1, RR - 1)];

        float f0 = (g > 0)      ? 0.625f : 0.0f;
        float f1 = (g > 0)      ? 0.875f : 0.0f;
        float f2 = (g < RR - 1) ? 0.125f : 0.0f;
        float f3 = (g < RR - 1) ? 0.375f : 0.0f;

        hr[0] = hm.x * (1.0f - f0) + h0.x * f0;  hi[0] = hm.y * (1.0f - f0) + h0.y * f0;
        hr[1] = hm.x * (1.0f - f1) + h0.x * f1;  hi[1] = hm.y * (1.0f - f1) + h0.y * f1;
        hr[2] = h0.x * (1.0f - f2) + hp.x * f2;  hi[2] = h0.y * (1.0f - f2) + hp.y * f2;
        hr[3] = h0.x * (1.0f - f3) + hp.x * f3;  hi[3] = h0.y * (1.0f - f3) + hp.y * f3;

        float pms, pmc, mss, msc;
        sincosf(WF * (float)((mm * l0) % SL), &pms, &pmc);
        sincosf(WF * (float)mm, &mss, &msc);

        float cr[4], cc[4];
#pragma unroll
        for (int j = 0; j < 4; j++) {
            pr[j] = pmc; pi[j] = pms;
            // recon contribution: h_interp * conj(ph_m)
            cr[j] = hr[j] * pmc + hi[j] * pms;
            cc[j] = hi[j] * pmc - hr[j] * pms;
            if (j < 3) {
                float nc = pmc * msc - pms * mss;
                float ns = pmc * mss + pms * msc;
                pmc = nc; pms = ns;
            }
        }
        float4* dst = (float4*)&shc[s][lane * 8];
        dst[0] = make_float4(cr[0], cc[0], cr[1], cc[1]);
        dst[1] = make_float4(cr[2], cc[2], cr[3], cc[3]);
    }
    __syncthreads();

    // residual reduction
    {
        int ll   = threadIdx.x >> 1;
        int comp = threadIdx.x & 1;
        int lg   = lbase + ll;
        if (lg < SL) {
            float sum = 0.0f;
#pragma unroll
            for (int ss2 = 0; ss2 < SS; ss2++) sum += shc[ss2][ll * 2 + comp];
            const float* ls0 = comp ? lsi : lsr;
            shres[ll * 2 + comp] = ls0[(size_t)ba * SL + lg] - sum;
        }
    }
    __syncthreads();

    if (act) {
        float pts, ptc, tss, tsc;
        sincosf(WF * (float)((tt * l0) % SL), &pts, &ptc);
        sincosf(WF * (float)tt, &tss, &tsc);

        float4 r01 = *(float4*)&shres[lane * 8];
        float4 r23 = *(float4*)&shres[lane * 8 + 4];
        float rres[4] = {r01.x, r01.z, r23.x, r23.z};
        float rims[4] = {r01.y, r01.w, r23.y, r23.w};

        float4 outr, outi;
        float* orp = &outr.x;
        float* oip = &outi.x;
#pragma unroll
        for (int j = 0; j < 4; j++) {
            float wr = hr[j] + rres[j] * pr[j] - rims[j] * pi[j];
            float wi = hi[j] + rres[j] * pi[j] + rims[j] * pr[j];
            orp[j] = wr * ptc + wi * pts;
            oip[j] = wi * ptc - wr * pts;
            if (j < 3) {
                float nc = ptc * tsc - pts * tss;
                float ns = ptc * tss + pts * tsc;
                ptc = nc; pts = ns;
            }
        }

        const size_t TOT = (size_t)SS * BB * AA * SL;
        size_t off = ((size_t)sb * AA + a) * SL + (size_t)l0;
        *(float4*)(out + off)       = outr;
        *(float4*)(out + TOT + off) = outi;
    }
}

// ---------------------------------------------------------------------------
extern "C" void kernel_launch(void* const* d_in, const int* in_sizes, int n_in,
                              void* d_out, int out_size) {
    (void)in_sizes; (void)n_in; (void)out_size;
    const float* lsr = (const float*)d_in[0];
    const float* lsi = (const float*)d_in[1];
    const int*   cs  = (const int*)d_in[2];
    float*       out = (float*)d_out;

    k_main<<<SS * BB, 128>>>(lsr, lsi, cs);
    k_final<<<BB * AA * NTILE, 256>>>(lsr, lsi, out);
}

// round 5
// speedup vs baseline: 4.9257x; 1.1142x over previous
#include <cuda_runtime.h>
#include <cstdint>

#define SL   3264            // seq length L
#define KK   12
#define LPK  (SL / KK)       // 272
#define SS   8               // streams
#define BB   64              // batch
#define AA   4               // antennas
#define RR   (SL / 4)        // 816 (L / LOCC)
#define NOFF 21              // delay candidates -10..10
#define TILE 128             // l-tile for k_final
#define NTILE 26             // ceil(3264/128)
#define NITER 51             // SL / 64 l-pairs per warp

// ---- scratch (device-global: allocation-free contract) ----
__device__ int    g_m[SS * BB];                   // (t_off + ideal_peak) mod L
__device__ int    g_tt[SS * BB];                  // t_off mod L
__device__ float2 g_havg[SS * BB * AA * RR];      // OCC-averaged channel, 13.4 MB

// ---- packed f32x2 helpers (sm_103a dual-lane fp32) ----
#define F2MUL(o, a, b)    asm("mul.rn.f32x2 %0, %1, %2;"      : "=l"(o) : "l"(a), "l"(b))
#define F2FMA(o, a, b, c) asm("fma.rn.f32x2 %0, %1, %2, %3;"  : "=l"(o) : "l"(a), "l"(b), "l"(c))
#define F2ADD(o, a, b)    asm("add.rn.f32x2 %0, %1, %2;"      : "=l"(o) : "l"(a), "l"(b))
#define SGNMASK 0x8000000080000000ULL

static __device__ __forceinline__ uint64_t pk2(float lo, float hi) {
    uint64_t r; asm("mov.b64 %0, {%1, %2};" : "=l"(r) : "f"(lo), "f"(hi)); return r;
}
static __device__ __forceinline__ float lo2(uint64_t v) {
    float a, b; asm("mov.b64 {%0, %1}, %2;" : "=f"(a), "=f"(b) : "l"(v)); return a;
}
static __device__ __forceinline__ float hi2(uint64_t v) {
    float a, b; asm("mov.b64 {%0, %1}, %2;" : "=f"(a), "=f"(b) : "l"(v)); return b;
}

// fp32 2*pi/L, exactly round(2*pi/3264) like the reference
#define WF ((float)(6.283185307179586476925286766559 / 3264.0))

// fast phasor: e^{i th k}, k in [0, SL); reduce to (-pi, pi] for MUFU accuracy
static __device__ __forceinline__ float2 phasor(int k) {
    if (k > SL / 2) k -= SL;
    float s, c;
    __sincosf(WF * (float)k, &s, &c);
    return make_float2(c, s);
}

// ---------------------------------------------------------------------------
// k_main: fused timing-offset search (phase A, Chebyshev) + OCC avg (phase B).
//   One block per (s,b), 128 threads, warp = antenna.
// ---------------------------------------------------------------------------
__global__ void __launch_bounds__(128, 4)
k_main(const float* __restrict__ lsr, const float* __restrict__ lsi,
       const int* __restrict__ cs) {
    const int sb   = blockIdx.x;
    const int s    = sb / BB;
    const int a    = threadIdx.x >> 5;   // warp = antenna
    const int lane = threadIdx.x & 31;

    __shared__ float2 sh[AA][NOFF];
    __shared__ float  shpow[NOFF];
    __shared__ int    sh_mm;

    const int ideal = ((KK - cs[s]) % KK) * LPK;   // in [0, SL)
    const int n0    = ideal;

    const float* br = lsr + ((size_t)sb * AA + a) * SL;
    const float* bi = lsi + ((size_t)sb * AA + a) * SL;

    // ---- per-thread phasor seeds (MUFU) ----
    const int lp = lane * 2;              // l pair start; stride 64/iter
    float2 u0 = phasor(lp);
    float2 u1 = phasor(lp + 1);
    uint64_t ur2 = pk2(u0.x, u1.x), ui2 = pk2(u0.y, u1.y);

    int ca = (n0 * lp) % SL;
    int cb = ca + n0; if (cb >= SL) cb -= SL;
    float2 c0 = phasor(ca);
    float2 c1 = phasor(cb);
    uint64_t cr2 = pk2(c0.x, c1.x), ci2 = pk2(c0.y, c1.y);

    float2 su = phasor(64);
    uint64_t sur2 = pk2(su.x, su.x), sui2 = pk2(su.y, su.y);
    float2 sc = phasor((n0 * 64) % SL);
    uint64_t scr2 = pk2(sc.x, sc.x), sci2 = pk2(sc.y, sc.y);

    uint64_t accr[NOFF], acci[NOFF];
#pragma unroll
    for (int d = 0; d < NOFF; d++) { accr[d] = 0ULL; acci[d] = 0ULL; }

    int l = lp;
#pragma unroll 1
    for (int it = 0; it < NITER; ++it) {
        uint64_t xr2 = *(const uint64_t*)(br + l);
        uint64_t xi2 = *(const uint64_t*)(bi + l);
        l += 64;

        // z = x * c
        uint64_t t1, t2, zr, zi;
        F2MUL(t1, xi2, ci2); t1 ^= SGNMASK;
        F2MUL(t2, xi2, cr2);
        F2FMA(zr, xr2, cr2, t1);
        F2FMA(zi, xr2, ci2, t2);

        F2ADD(accr[10], accr[10], zr);
        F2ADD(acci[10], acci[10], zi);

        // w1 = z * u
        uint64_t w1r, w1i;
        F2MUL(t1, zi, ui2); t1 ^= SGNMASK;
        F2MUL(t2, zi, ur2);
        F2FMA(w1r, zr, ur2, t1);
        F2FMA(w1i, zr, ui2, t2);

        F2ADD(accr[11], accr[11], w1r);
        F2ADD(acci[11], acci[11], w1i);

        // Chebyshev coefficient: tc = 2 Re(u); ntc = -tc
        uint64_t tc, ntc;
        F2ADD(tc, ur2, ur2);
        ntc = tc ^ SGNMASK;

        // forward chain: v_{d+1} = (+-tc) v_d + v_{d-1}; |acc| sign-invariant
        {
            uint64_t fpr = zr, fpi = zi, fcr = w1r, fci = w1i;
#pragma unroll
            for (int d = 1; d <= 9; ++d) {
                uint64_t co = (d & 1) ? ntc : tc;
                uint64_t nr, ni;
                F2FMA(nr, co, fcr, fpr);
                F2FMA(ni, co, fci, fpi);
                fpr = fcr; fpi = fci; fcr = nr; fci = ni;
                F2ADD(accr[11 + d], accr[11 + d], nr);
                F2ADD(acci[11 + d], acci[11 + d], ni);
            }
        }
        // backward chain: seed v'_1 = ntc*z + w1 ( = -w_{-1} )
        {
            uint64_t bpr = zr, bpi = zi, bcr, bci;
            F2FMA(bcr, ntc, zr, w1r);
            F2FMA(bci, ntc, zi, w1i);
            F2ADD(accr[9], accr[9], bcr);
            F2ADD(acci[9], acci[9], bci);
#pragma unroll
            for (int d = 1; d <= 9; ++d) {
                uint64_t co = (d & 1) ? tc : ntc;
                uint64_t nr, ni;
                F2FMA(nr, co, bcr, bpr);
                F2FMA(ni, co, bci, bpi);
                bpr = bcr; bpi = bci; bcr = nr; bci = ni;
                F2ADD(accr[9 - d], accr[9 - d], nr);
                F2ADD(acci[9 - d], acci[9 - d], ni);
            }
        }
        // u *= su ; c *= sc
        uint64_t nr;
        F2MUL(t1, ui2, sui2); t1 ^= SGNMASK;
        F2MUL(t2, ui2, sur2);
        F2FMA(nr,  ur2, sur2, t1);
        F2FMA(ui2, ur2, sui2, t2);
        ur2 = nr;
        F2MUL(t1, ci2, sci2); t1 ^= SGNMASK;
        F2MUL(t2, ci2, scr2);
        F2FMA(nr,  cr2, scr2, t1);
        F2FMA(ci2, cr2, sci2, t2);
        cr2 = nr;
    }

    // reduce: packed halves -> scalar, warp shfl-sum
#pragma unroll
    for (int d = 0; d < NOFF; d++) {
        float rr = lo2(accr[d]) + hi2(accr[d]);
        float ii = lo2(acci[d]) + hi2(acci[d]);
#pragma unroll
        for (int o = 16; o > 0; o >>= 1) {
            rr += __shfl_xor_sync(0xFFFFFFFFu, rr, o);
            ii += __shfl_xor_sync(0xFFFFFFFFu, ii, o);
        }
        if (lane == 0) sh[a][d] = make_float2(rr, ii);
    }
    __syncthreads();

    if (threadIdx.x < NOFF) {
        int d = threadIdx.x;
        float p = 0.0f;
#pragma unroll
        for (int aa = 0; aa < AA; aa++) {
            float re = sh[aa][d].x, im = sh[aa][d].y;
            p += re * re + im * im;
        }
        shpow[d] = p;
    }
    __syncthreads();

    if (threadIdx.x == 0) {
        int   best = 0;
        float bp   = shpow[0];
        for (int j = 1; j < NOFF; j++)
            if (shpow[j] > bp) { bp = shpow[j]; best = j; }  // first-max tie rule
        int toff = best - 10;
        int mmv  = (((toff + ideal) % SL) + SL) % SL;
        g_m[sb]  = mmv;
        g_tt[sb] = ((toff % SL) + SL) % SL;
        sh_mm    = mmv;
    }
    __syncthreads();

    // ---- phase B: OCC averaging, trig-free via phasor recurrences ----
    const int mmv = sh_mm;
    float2 msv = phasor(mmv);                       // inner step e^{i th mm}
    float2 spv = phasor((int)(((long long)mmv * 512) % SL)); // per-iter step (r += 128)
    float2 sd0 = phasor((int)(((long long)mmv * 4 * threadIdx.x) % SL)); // seed

#pragma unroll
    for (int a2 = 0; a2 < AA; a2++) {
        const float* br2 = lsr + ((size_t)sb * AA + a2) * SL;
        const float* bi2 = lsi + ((size_t)sb * AA + a2) * SL;
        float2* ho = g_havg + ((size_t)sb * AA + a2) * RR;
        float pc = sd0.x, ps = sd0.y;
        for (int r = threadIdx.x; r < RR; r += 128) {
            int l0 = 4 * r;
            float4 xr = *(const float4*)(br2 + l0);
            float4 xi = *(const float4*)(bi2 + l0);
            float xrv[4] = {xr.x, xr.y, xr.z, xr.w};
            float xiv[4] = {xi.x, xi.y, xi.z, xi.w};
            float qc = pc, qs = ps;
            float sr = 0.0f, si = 0.0f;
#pragma unroll
            for (int j = 0; j < 4; j++) {
                sr += xrv[j] * qc - xiv[j] * qs;
                si += xrv[j] * qs + xiv[j] * qc;
                if (j < 3) {
                    float nc = qc * msv.x - qs * msv.y;
                    float ns = qc * msv.y + qs * msv.x;
                    qc = nc; qs = ns;
                }
            }
            ho[r] = make_float2(sr * 0.25f, si * 0.25f);
            // advance seed by step (r += 128)
            float nc = pc * spv.x - ps * spv.y;
            float ns = pc * spv.y + ps * spv.x;
            pc = nc; ps = ns;
        }
    }
}

// ---------------------------------------------------------------------------
// k_final: warp-per-stream over a 128-l tile for one (b,a).
// ---------------------------------------------------------------------------
__global__ void __launch_bounds__(256)
k_final(const float* __restrict__ lsr, const float* __restrict__ lsi,
        float* __restrict__ out) {
    const int blk  = blockIdx.x;
    const int ba   = blk / NTILE;
    const int tile = blk % NTILE;
    const int a    = ba % AA;
    const int b    = ba / AA;
    const int s    = threadIdx.x >> 5;   // warp = stream
    const int lane = threadIdx.x & 31;

    const int lbase = tile * TILE;
    const int l0    = lbase + lane * 4;
    const bool act  = (l0 < SL);

    __shared__ float shc[SS][2 * TILE];   // recon contributions
    __shared__ float shres[2 * TILE];     // residual

    const int sb = s * BB + b;
    const int mm = g_m[sb];
    const int tt = g_tt[sb];
    const float2* hv = g_havg + ((size_t)sb * AA + a) * RR;

    float hr[4], hi[4], pr[4], pi[4];

    if (act) {
        int g = l0 >> 2;
        float2 hm = hv[max(g - 1, 0)];
        float2 h0 = hv[g];
        float2 hp = hv[min(g + 1, RR - 1)];

        float f0 = (g > 0)      ? 0.625f : 0.0f;
        float f1 = (g > 0)      ? 0.875f : 0.0f;
        float f2 = (g < RR - 1) ? 0.125f : 0.0f;
        float f3 = (g < RR - 1) ? 0.375f : 0.0f;

        hr[0] = hm.x * (1.0f - f0) + h0.x * f0;  hi[0] = hm.y * (1.0f - f0) + h0.y * f0;
        hr[1] = hm.x * (1.0f - f1) + h0.x * f1;  hi[1] = hm.y * (1.0f - f1) + h0.y * f1;
        hr[2] = h0.x * (1.0f - f2) + hp.x * f2;  hi[2] = h0.y * (1.0f - f2) + hp.y * f2;
        hr[3] = h0.x * (1.0f - f3) + hp.x * f3;  hi[3] = h0.y * (1.0f - f3) + hp.y * f3;

        float2 pm = phasor((mm * l0) % SL);
        float2 ms = phasor(mm);
        float pmc = pm.x, pms = pm.y;

        float cr[4], cc[4];
#pragma unroll
        for (int j = 0; j < 4; j++) {
            pr[j] = pmc; pi[j] = pms;
            cr[j] = hr[j] * pmc + hi[j] * pms;
            cc[j] = hi[j] * pmc - hr[j] * pms;
            if (j < 3) {
                float nc = pmc * ms.x - pms * ms.y;
                float ns = pmc * ms.y + pms * ms.x;
                pmc = nc; pms = ns;
            }
        }
        float4* dst = (float4*)&shc[s][lane * 8];
        dst[0] = make_float4(cr[0], cc[0], cr[1], cc[1]);
        dst[1] = make_float4(cr[2], cc[2], cr[3], cc[3]);
    }
    __syncthreads();

    // residual reduction
    {
        int ll   = threadIdx.x >> 1;
        int comp = threadIdx.x & 1;
        int lg   = lbase + ll;
        if (lg < SL) {
            float sum = 0.0f;
#pragma unroll
            for (int ss2 = 0; ss2 < SS; ss2++) sum += shc[ss2][ll * 2 + comp];
            const float* ls0 = comp ? lsi : lsr;
            shres[ll * 2 + comp] = ls0[(size_t)ba * SL + lg] - sum;
        }
    }
    __syncthreads();

    if (act) {
        float2 pt = phasor((tt * l0) % SL);
        float2 ts = phasor(tt);
        float ptc = pt.x, pts = pt.y;

        float4 r01 = *(float4*)&shres[lane * 8];
        float4 r23 = *(float4*)&shres[lane * 8 + 4];
        float rres[4] = {r01.x, r01.z, r23.x, r23.z};
        float rims[4] = {r01.y, r01.w, r23.y, r23.w};

        float4 outr, outi;
        float* orp = &outr.x;
        float* oip = &outi.x;
#pragma unroll
        for (int j = 0; j < 4; j++) {
            float wr = hr[j] + rres[j] * pr[j] - rims[j] * pi[j];
            float wi = hi[j] + rres[j] * pi[j] + rims[j] * pr[j];
            orp[j] = wr * ptc + wi * pts;
            oip[j] = wi * ptc - wr * pts;
            if (j < 3) {
                float nc = ptc * ts.x - pts * ts.y;
                float ns = ptc * ts.y + pts * ts.x;
                ptc = nc; pts = ns;
            }
        }

        const size_t TOT = (size_t)SS * BB * AA * SL;
        size_t off = ((size_t)sb * AA + a) * SL + (size_t)l0;
        *(float4*)(out + off)       = outr;
        *(float4*)(out + TOT + off) = outi;
    }
}

// ---------------------------------------------------------------------------
extern "C" void kernel_launch(void* const* d_in, const int* in_sizes, int n_in,
                              void* d_out, int out_size) {
    (void)in_sizes; (void)n_in; (void)out_size;
    const float* lsr = (const float*)d_in[0];
    const float* lsi = (const float*)d_in[1];
    const int*   cs  = (const int*)d_in[2];
    float*       out = (float*)d_out;

    k_main<<<SS * BB, 128>>>(lsr, lsi, cs);
    k_final<<<BB * AA * NTILE, 256>>>(lsr, lsi, out);
}

// round 6
// speedup vs baseline: 6.2104x; 1.2608x over previous
#include <cuda_runtime.h>
#include <cstdint>

#define SL   3264            // seq length L
#define KK   12
#define LPK  (SL / KK)       // 272
#define SS   8               // streams
#define BB   64              // batch
#define AA   4               // antennas
#define RR   (SL / 4)        // 816 (L / LOCC)
#define NOFF 21              // delay candidates -10..10
#define TILE 128             // l-tile for k_final
#define NTILE 26             // ceil(3264/128)
#define PDIM 816             // decimated length L/4

// ---- scratch (device-global: allocation-free contract) ----
__device__ int    g_m[SS * BB];                   // (t_off + ideal_peak) mod L
__device__ int    g_tt[SS * BB];                  // t_off mod L
__device__ float2 g_havg[SS * BB * AA * RR];      // OCC-averaged channel, 13.4 MB

// ---- packed f32x2 helpers (sm_103a dual-lane fp32) ----
#define F2MUL(o, a, b)    asm("mul.rn.f32x2 %0, %1, %2;"      : "=l"(o) : "l"(a), "l"(b))
#define F2FMA(o, a, b, c) asm("fma.rn.f32x2 %0, %1, %2, %3;"  : "=l"(o) : "l"(a), "l"(b), "l"(c))
#define F2ADD(o, a, b)    asm("add.rn.f32x2 %0, %1, %2;"      : "=l"(o) : "l"(a), "l"(b))
#define SGNMASK 0x8000000080000000ULL

static __device__ __forceinline__ uint64_t pk2(float lo, float hi) {
    uint64_t r; asm("mov.b64 %0, {%1, %2};" : "=l"(r) : "f"(lo), "f"(hi)); return r;
}
static __device__ __forceinline__ float lo2(uint64_t v) {
    float a, b; asm("mov.b64 {%0, %1}, %2;" : "=f"(a), "=f"(b) : "l"(v)); return a;
}
static __device__ __forceinline__ float hi2(uint64_t v) {
    float a, b; asm("mov.b64 {%0, %1}, %2;" : "=f"(a), "=f"(b) : "l"(v)); return b;
}
static __device__ __forceinline__ uint64_t splat(float v) { return pk2(v, v); }

// fp32 2*pi/L, matching reference fp32 angle math
#define WF ((float)(6.283185307179586476925286766559 / 3264.0))

// fast phasor: e^{i th k}, k in [0, SL); reduce to (-pi, pi] for MUFU accuracy
static __device__ __forceinline__ float2 phasor(int k) {
    if (k > SL / 2) k -= SL;
    float s, c;
    __sincosf(WF * (float)k, &s, &c);
    return make_float2(c, s);
}

static __device__ __forceinline__ int modL(int x) { x %= SL; return x < 0 ? x + SL : x; }

// packed complex in-place multiply: (ar,ai) *= (br,bi)
#define CMUL(ar, ai, br, bi) do {            \
    uint64_t _m, _nr;                        \
    F2MUL(_m, ai, bi); _m ^= SGNMASK;        \
    F2FMA(_nr, ar, br, _m);                  \
    F2MUL(_m, ai, br);                       \
    F2FMA(ai, ar, bi, _m);                   \
    ar = _nr;                                \
} while (0)

// Evaluate one residue class: acc_j += (+-) W * seed * phi^j, j = 0..S-1
// (Chebyshev 3-term chain with alternating-sign substitution; signs are
//  consistent per j across iterations, and only |acc|^2 is consumed.)
template <int S>
static __device__ __forceinline__ void eval_class(
    uint64_t Wr, uint64_t Wi, uint64_t sr, uint64_t si,
    uint64_t phir, uint64_t phii, uint64_t tc, uint64_t ntc,
    uint64_t* accr, uint64_t* acci)
{
    uint64_t m, v0r, v0i;
    F2MUL(m, Wi, si); m ^= SGNMASK;
    F2FMA(v0r, Wr, sr, m);
    F2MUL(m, Wi, sr);
    F2FMA(v0i, Wr, si, m);
    F2ADD(accr[0], accr[0], v0r);
    F2ADD(acci[0], acci[0], v0i);

    uint64_t v1r, v1i;
    F2MUL(m, v0i, phii); m ^= SGNMASK;
    F2FMA(v1r, v0r, phir, m);
    F2MUL(m, v0i, phir);
    F2FMA(v1i, v0r, phii, m);
    F2ADD(accr[1], accr[1], v1r);
    F2ADD(acci[1], acci[1], v1i);

    uint64_t pr = v0r, pi_ = v0i, cr = v1r, ci_ = v1i;
#pragma unroll
    for (int j = 2; j < S; j++) {
        uint64_t co = (j & 1) ? tc : ntc;   // -tc, +tc, -tc, ...
        uint64_t nr, ni;
        F2FMA(nr, co, cr, pr);
        F2FMA(ni, co, ci_, pi_);
        pr = cr; pi_ = ci_; cr = nr; ci_ = ni;
        F2ADD(accr[j], accr[j], nr);
        F2ADD(acci[j], acci[j], ni);
    }
}

// packed-halves + warp reduce, lane0 writes sh row
static __device__ __forceinline__ void reduce_to(
    float2* shrow, int idx, uint64_t ar, uint64_t ai, int lane)
{
    float rr = lo2(ar) + hi2(ar);
    float ii = lo2(ai) + hi2(ai);
#pragma unroll
    for (int o = 16; o > 0; o >>= 1) {
        rr += __shfl_xor_sync(0xFFFFFFFFu, rr, o);
        ii += __shfl_xor_sync(0xFFFFFFFFu, ii, o);
    }
    if (lane == 0) shrow[idx] = make_float2(rr, ii);
}

// ---------------------------------------------------------------------------
// k_main: phase A = radix-4-decimated candidate DFT (two passes over residue
// classes), phase B = OCC averaging. One block per (s,b), warp = antenna.
//
//   X(n0+d) = sum_p e^{i th (n0+d) p} * W_p[d mod 4],
//   W_p[k]  = sum_q x_{p+816q} i^{kq}   (multiplier-free FFT4; th*816 = pi/2,
//   and n0 = 272*j is divisible by 4 so the chirp q-factor vanishes)
// ---------------------------------------------------------------------------
__global__ void __launch_bounds__(128, 4)
k_main(const float* __restrict__ lsr, const float* __restrict__ lsi,
       const int* __restrict__ cs) {
    const int sb   = blockIdx.x;
    const int s    = sb / BB;
    const int a    = threadIdx.x >> 5;   // warp = antenna
    const int lane = threadIdx.x & 31;

    __shared__ float2 sh[AA][NOFF];
    __shared__ float  shpow[NOFF];
    __shared__ int    sh_mm;

    const int ideal = ((KK - cs[s]) % KK) * LPK;   // in [0, SL), multiple of 4
    const int n0    = ideal;

    const float* br = lsr + ((size_t)sb * AA + a) * SL;
    const float* bi = lsi + ((size_t)sb * AA + a) * SL;

    const int p0 = 2 * lane;     // packed pair (p0, p0+1); advance 64/iter

    // phi = e^{i 4 th p} packed; step e^{i 256 th} splat (shared by passes)
    const float2 psc = phasor(256 % SL);
    const uint64_t pstr = splat(psc.x), psti = splat(psc.y);

    // ======================= PASS 0: classes k=0 (dmin=-8, S=5),
    //                                  k=2 (dmin=-10, S=6) =================
    {
        uint64_t a0r[5], a0i[5], a2r[6], a2i[6];
#pragma unroll
        for (int j = 0; j < 5; j++) { a0r[j] = a0i[j] = 0ULL; }
#pragma unroll
        for (int j = 0; j < 6; j++) { a2r[j] = a2i[j] = 0ULL; }

        const int f0 = n0 - 8, f2 = n0 - 10;
        float2 ea = phasor(modL(f0 * p0)), eb = phasor(modL(f0 * (p0 + 1)));
        uint64_t s0r = pk2(ea.x, eb.x), s0i = pk2(ea.y, eb.y);
        ea = phasor(modL(f2 * p0)); eb = phasor(modL(f2 * (p0 + 1)));
        uint64_t s2r = pk2(ea.x, eb.x), s2i = pk2(ea.y, eb.y);

        float2 st = phasor(modL(f0 * 64));
        uint64_t st0r = splat(st.x), st0i = splat(st.y);
        st = phasor(modL(f2 * 64));
        uint64_t st2r = splat(st.x), st2i = splat(st.y);

        float2 pa = phasor(modL(4 * p0)), pb = phasor(modL(4 * p0 + 4));
        uint64_t phir = pk2(pa.x, pb.x), phii = pk2(pa.y, pb.y);

        int p = p0;
#pragma unroll 1
        for (int it = 0; it < 13; ++it, p += 64) {
            const bool v = (p < PDIM);
            uint64_t xr0 = v ? *(const uint64_t*)(br + p)            : 0ULL;
            uint64_t xr1 = v ? *(const uint64_t*)(br + p + PDIM)     : 0ULL;
            uint64_t xr2 = v ? *(const uint64_t*)(br + p + 2 * PDIM) : 0ULL;
            uint64_t xr3 = v ? *(const uint64_t*)(br + p + 3 * PDIM) : 0ULL;
            uint64_t xi0 = v ? *(const uint64_t*)(bi + p)            : 0ULL;
            uint64_t xi1 = v ? *(const uint64_t*)(bi + p + PDIM)     : 0ULL;
            uint64_t xi2 = v ? *(const uint64_t*)(bi + p + 2 * PDIM) : 0ULL;
            uint64_t xi3 = v ? *(const uint64_t*)(bi + p + 3 * PDIM) : 0ULL;

            // half-FFT4 (even outputs): W0 = (z0+z2)+(z1+z3), W2 = (z0+z2)-(z1+z3)
            uint64_t t0r, t0i, t2r, t2i, W0r, W0i, W2r, W2i;
            F2ADD(t0r, xr0, xr2); F2ADD(t0i, xi0, xi2);
            F2ADD(t2r, xr1, xr3); F2ADD(t2i, xi1, xi3);
            F2ADD(W0r, t0r, t2r); F2ADD(W0i, t0i, t2i);
            uint64_t n1 = t2r ^ SGNMASK, n2 = t2i ^ SGNMASK;
            F2ADD(W2r, t0r, n1); F2ADD(W2i, t0i, n2);

            uint64_t tc, ntc;
            F2ADD(tc, phir, phir); ntc = tc ^ SGNMASK;

            eval_class<5>(W0r, W0i, s0r, s0i, phir, phii, tc, ntc, a0r, a0i);
            eval_class<6>(W2r, W2i, s2r, s2i, phir, phii, tc, ntc, a2r, a2i);

            CMUL(s0r, s0i, st0r, st0i);
            CMUL(s2r, s2i, st2r, st2i);
            CMUL(phir, phii, pstr, psti);
        }
#pragma unroll
        for (int j = 0; j < 5; j++) reduce_to(&sh[a][0], 2 + 4 * j, a0r[j], a0i[j], lane);
#pragma unroll
        for (int j = 0; j < 6; j++) reduce_to(&sh[a][0], 0 + 4 * j, a2r[j], a2i[j], lane);
    }

    // ======================= PASS 1: classes k=1 (dmin=-7, S=5),
    //                                  k=3 (dmin=-9, S=5) ==================
    {
        uint64_t a1r[5], a1i[5], a3r[5], a3i[5];
#pragma unroll
        for (int j = 0; j < 5; j++) { a1r[j] = a1i[j] = 0ULL; a3r[j] = a3i[j] = 0ULL; }

        const int f1 = n0 - 7, f3 = n0 - 9;
        float2 ea = phasor(modL(f1 * p0)), eb = phasor(modL(f1 * (p0 + 1)));
        uint64_t s1r = pk2(ea.x, eb.x), s1i = pk2(ea.y, eb.y);
        ea = phasor(modL(f3 * p0)); eb = phasor(modL(f3 * (p0 + 1)));
        uint64_t s3r = pk2(ea.x, eb.x), s3i = pk2(ea.y, eb.y);

        float2 st = phasor(modL(f1 * 64));
        uint64_t st1r = splat(st.x), st1i = splat(st.y);
        st = phasor(modL(f3 * 64));
        uint64_t st3r = splat(st.x), st3i = splat(st.y);

        float2 pa = phasor(modL(4 * p0)), pb = phasor(modL(4 * p0 + 4));
        uint64_t phir = pk2(pa.x, pb.x), phii = pk2(pa.y, pb.y);

        int p = p0;
#pragma unroll 1
        for (int it = 0; it < 13; ++it, p += 64) {
            const bool v = (p < PDIM);
            uint64_t xr0 = v ? *(const uint64_t*)(br + p)            : 0ULL;
            uint64_t xr1 = v ? *(const uint64_t*)(br + p + PDIM)     : 0ULL;
            uint64_t xr2 = v ? *(const uint64_t*)(br + p + 2 * PDIM) : 0ULL;
            uint64_t xr3 = v ? *(const uint64_t*)(br + p + 3 * PDIM) : 0ULL;
            uint64_t xi0 = v ? *(const uint64_t*)(bi + p)            : 0ULL;
            uint64_t xi1 = v ? *(const uint64_t*)(bi + p + PDIM)     : 0ULL;
            uint64_t xi2 = v ? *(const uint64_t*)(bi + p + 2 * PDIM) : 0ULL;
            uint64_t xi3 = v ? *(const uint64_t*)(bi + p + 3 * PDIM) : 0ULL;

            // half-FFT4 (odd outputs): t1 = z0-z2, t3 = z1-z3,
            // W1 = t1 + i*t3, W3 = t1 - i*t3
            uint64_t nxr2 = xr2 ^ SGNMASK, nxi2 = xi2 ^ SGNMASK;
            uint64_t nxr3 = xr3 ^ SGNMASK, nxi3 = xi3 ^ SGNMASK;
            uint64_t t1r, t1i, t3r, t3i;
            F2ADD(t1r, xr0, nxr2); F2ADD(t1i, xi0, nxi2);
            F2ADD(t3r, xr1, nxr3); F2ADD(t3i, xi1, nxi3);
            uint64_t nt3i = t3i ^ SGNMASK, nt3r = t3r ^ SGNMASK;
            uint64_t W1r, W1i, W3r, W3i;
            F2ADD(W1r, t1r, nt3i); F2ADD(W1i, t1i, t3r);
            F2ADD(W3r, t1r, t3i);  F2ADD(W3i, t1i, nt3r);

            uint64_t tc, ntc;
            F2ADD(tc, phir, phir); ntc = tc ^ SGNMASK;

            eval_class<5>(W1r, W1i, s1r, s1i, phir, phii, tc, ntc, a1r, a1i);
            eval_class<5>(W3r, W3i, s3r, s3i, phir, phii, tc, ntc, a3r, a3i);

            CMUL(s1r, s1i, st1r, st1i);
            CMUL(s3r, s3i, st3r, st3i);
            CMUL(phir, phii, pstr, psti);
        }
#pragma unroll
        for (int j = 0; j < 5; j++) reduce_to(&sh[a][0], 3 + 4 * j, a1r[j], a1i[j], lane);
#pragma unroll
        for (int j = 0; j < 5; j++) reduce_to(&sh[a][0], 1 + 4 * j, a3r[j], a3i[j], lane);
    }
    __syncthreads();

    // power + argmax (first-max tie rule, same as reference)
    if (threadIdx.x < NOFF) {
        int d = threadIdx.x;
        float p = 0.0f;
#pragma unroll
        for (int aa = 0; aa < AA; aa++) {
            float re = sh[aa][d].x, im = sh[aa][d].y;
            p += re * re + im * im;
        }
        shpow[d] = p;
    }
    __syncthreads();

    if (threadIdx.x == 0) {
        int   best = 0;
        float bp   = shpow[0];
        for (int j = 1; j < NOFF; j++)
            if (shpow[j] > bp) { bp = shpow[j]; best = j; }
        int toff = best - 10;
        int mmv  = modL(toff + ideal);
        g_m[sb]  = mmv;
        g_tt[sb] = modL(toff);
        sh_mm    = mmv;
    }
    __syncthreads();

    // ---- phase B: OCC averaging, trig-free via phasor recurrences ----
    const int mmv = sh_mm;
    float2 msv = phasor(mmv);                                       // e^{i th mm}
    float2 spv = phasor((int)(((long long)mmv * 512) % SL));        // r += 128 step
    float2 sd0 = phasor((int)(((long long)mmv * 4 * threadIdx.x) % SL));

#pragma unroll
    for (int a2 = 0; a2 < AA; a2++) {
        const float* br2 = lsr + ((size_t)sb * AA + a2) * SL;
        const float* bi2 = lsi + ((size_t)sb * AA + a2) * SL;
        float2* ho = g_havg + ((size_t)sb * AA + a2) * RR;
        float pc = sd0.x, ps = sd0.y;
        for (int r = threadIdx.x; r < RR; r += 128) {
            int l0 = 4 * r;
            float4 xr = *(const float4*)(br2 + l0);
            float4 xi = *(const float4*)(bi2 + l0);
            float xrv[4] = {xr.x, xr.y, xr.z, xr.w};
            float xiv[4] = {xi.x, xi.y, xi.z, xi.w};
            float qc = pc, qs = ps;
            float sr = 0.0f, si = 0.0f;
#pragma unroll
            for (int j = 0; j < 4; j++) {
                sr += xrv[j] * qc - xiv[j] * qs;
                si += xrv[j] * qs + xiv[j] * qc;
                if (j < 3) {
                    float nc = qc * msv.x - qs * msv.y;
                    float ns = qc * msv.y + qs * msv.x;
                    qc = nc; qs = ns;
                }
            }
            ho[r] = make_float2(sr * 0.25f, si * 0.25f);
            float nc = pc * spv.x - ps * spv.y;
            float ns = pc * spv.y + ps * spv.x;
            pc = nc; ps = ns;
        }
    }
}

// ---------------------------------------------------------------------------
// k_final: warp-per-stream over a 128-l tile for one (b,a).
// ---------------------------------------------------------------------------
__global__ void __launch_bounds__(256)
k_final(const float* __restrict__ lsr, const float* __restrict__ lsi,
        float* __restrict__ out) {
    const int blk  = blockIdx.x;
    const int ba   = blk / NTILE;
    const int tile = blk % NTILE;
    const int a    = ba % AA;
    const int b    = ba / AA;
    const int s    = threadIdx.x >> 5;   // warp = stream
    const int lane = threadIdx.x & 31;

    const int lbase = tile * TILE;
    const int l0    = lbase + lane * 4;
    const bool act  = (l0 < SL);

    __shared__ float shc[SS][2 * TILE];   // recon contributions
    __shared__ float shres[2 * TILE];     // residual

    const int sb = s * BB + b;
    const int mm = g_m[sb];
    const int tt = g_tt[sb];
    const float2* hv = g_havg + ((size_t)sb * AA + a) * RR;

    float hr[4], hi[4], pr[4], pi[4];

    if (act) {
        int g = l0 >> 2;
        float2 hm = hv[max(g - 1, 0)];
        float2 h0 = hv[g];
        float2 hp = hv[min(g + 1, RR - 1)];

        float f0 = (g > 0)      ? 0.625f : 0.0f;
        float f1 = (g > 0)      ? 0.875f : 0.0f;
        float f2 = (g < RR - 1) ? 0.125f : 0.0f;
        float f3 = (g < RR - 1) ? 0.375f : 0.0f;

        hr[0] = hm.x * (1.0f - f0) + h0.x * f0;  hi[0] = hm.y * (1.0f - f0) + h0.y * f0;
        hr[1] = hm.x * (1.0f - f1) + h0.x * f1;  hi[1] = hm.y * (1.0f - f1) + h0.y * f1;
        hr[2] = h0.x * (1.0f - f2) + hp.x * f2;  hi[2] = h0.y * (1.0f - f2) + hp.y * f2;
        hr[3] = h0.x * (1.0f - f3) + hp.x * f3;  hi[3] = h0.y * (1.0f - f3) + hp.y * f3;

        float2 pm = phasor((int)(((long long)mm * l0) % SL));
        float2 ms = phasor(mm);
        float pmc = pm.x, pms = pm.y;

        float cr[4], cc[4];
#pragma unroll
        for (int j = 0; j < 4; j++) {
            pr[j] = pmc; pi[j] = pms;
            cr[j] = hr[j] * pmc + hi[j] * pms;
            cc[j] = hi[j] * pmc - hr[j] * pms;
            if (j < 3) {
                float nc = pmc * ms.x - pms * ms.y;
                float ns = pmc * ms.y + pms * ms.x;
                pmc = nc; pms = ns;
            }
        }
        float4* dst = (float4*)&shc[s][lane * 8];
        dst[0] = make_float4(cr[0], cc[0], cr[1], cc[1]);
        dst[1] = make_float4(cr[2], cc[2], cr[3], cc[3]);
    }
    __syncthreads();

    // residual reduction
    {
        int ll   = threadIdx.x >> 1;
        int comp = threadIdx.x & 1;
        int lg   = lbase + ll;
        if (lg < SL) {
            float sum = 0.0f;
#pragma unroll
            for (int ss2 = 0; ss2 < SS; ss2++) sum += shc[ss2][ll * 2 + comp];
            const float* ls0 = comp ? lsi : lsr;
            shres[ll * 2 + comp] = ls0[(size_t)ba * SL + lg] - sum;
        }
    }
    __syncthreads();

    if (act) {
        float2 pt = phasor((int)(((long long)tt * l0) % SL));
        float2 ts = phasor(tt);
        float ptc = pt.x, pts = pt.y;

        float4 r01 = *(float4*)&shres[lane * 8];
        float4 r23 = *(float4*)&shres[lane * 8 + 4];
        float rres[4] = {r01.x, r01.z, r23.x, r23.z};
        float rims[4] = {r01.y, r01.w, r23.y, r23.w};

        float4 outr, outi;
        float* orp = &outr.x;
        float* oip = &outi.x;
#pragma unroll
        for (int j = 0; j < 4; j++) {
            float wr = hr[j] + rres[j] * pr[j] - rims[j] * pi[j];
            float wi = hi[j] + rres[j] * pi[j] + rims[j] * pr[j];
            orp[j] = wr * ptc + wi * pts;
            oip[j] = wi * ptc - wr * pts;
            if (j < 3) {
                float nc = ptc * ts.x - pts * ts.y;
                float ns = ptc * ts.y + pts * ts.x;
                ptc = nc; pts = ns;
            }
        }

        const size_t TOT = (size_t)SS * BB * AA * SL;
        size_t off = ((size_t)sb * AA + a) * SL + (size_t)l0;
        *(float4*)(out + off)       = outr;
        *(float4*)(out + TOT + off) = outi;
    }
}

// ---------------------------------------------------------------------------
extern "C" void kernel_launch(void* const* d_in, const int* in_sizes, int n_in,
                              void* d_out, int out_size) {
    (void)in_sizes; (void)n_in; (void)out_size;
    const float* lsr = (const float*)d_in[0];
    const float* lsi = (const float*)d_in[1];
    const int*   cs  = (const int*)d_in[2];
    float*       out = (float*)d_out;

    k_main<<<SS * BB, 128>>>(lsr, lsi, cs);
    k_final<<<BB * AA * NTILE, 256>>>(lsr, lsi, out);
}